// round 16
// baseline (speedup 1.0000x reference)
#include <cuda_runtime.h>
#include <cstdint>

#define NB 8
#define ND 512
#define NN 1024
#define NH 8
#define KD 64

__device__ float g_q[NB * NN * ND];
__device__ float g_kh[NB * NN * KD];
__device__ float g_kl[NB * NN * KD];
__device__ float g_vh[NB * NN * KD];
__device__ float g_vl[NB * NN * KD];
__device__ float g_o[NB * NN * ND];
__device__ float g_wkv[128 * ND];

// ---------------------------------------------------------------------------
// helpers
// ---------------------------------------------------------------------------
__device__ __forceinline__ float2 tf32_split(float x) {
    unsigned h, l;
    asm("cvt.rna.tf32.f32 %0, %1;" : "=r"(h) : "f"(x));
    float r = x - __uint_as_float(h);
    asm("cvt.rna.tf32.f32 %0, %1;" : "=r"(l) : "f"(r));
    return make_float2(__uint_as_float(h), __uint_as_float(l));
}

__device__ __forceinline__ unsigned tf32_hi(float x) {
    unsigned h;
    asm("cvt.rna.tf32.f32 %0, %1;" : "=r"(h) : "f"(x));
    return h;
}

__device__ __forceinline__ void mma_tf32(float* d, const unsigned* a,
                                         unsigned b0, unsigned b1) {
    asm("mma.sync.aligned.m16n8k8.row.col.f32.tf32.tf32.f32 "
        "{%0,%1,%2,%3}, {%4,%5,%6,%7}, {%8,%9}, {%0,%1,%2,%3};"
        : "+f"(d[0]), "+f"(d[1]), "+f"(d[2]), "+f"(d[3])
        : "r"(a[0]), "r"(a[1]), "r"(a[2]), "r"(a[3]), "r"(b0), "r"(b1));
}

// ---------------------------------------------------------------------------
// Kernel 1: pack wk/wv into row-major [j][d]
// ---------------------------------------------------------------------------
__global__ void pack_wkv_kernel(const float* __restrict__ kp,
                                const float* __restrict__ vp) {
    int idx = blockIdx.x * 256 + threadIdx.x;
    int j = idx >> 9, d = idx & 511;
    g_wkv[idx] = (j < 64) ? kp[d * 64 + j] : vp[d * 64 + (j - 64)];
}

// ---------------------------------------------------------------------------
// Kernel 2: QKV projection, split-tf32 mma.sync, m32n64 warp tiles.
// C[b][n][j] = sum_d rx[n][d] * W[j][d].
// CTA: 128(n) x 128(j), 8 warps (4m x 2n), warp = m32 x n64, K-chunk 16.
// Register prefetch of next chunk. Grid (5 jt, 8 nt, 8 b), 256 threads.
// jblk 0..3 -> Q, jblk 4 -> [K(64) | V(64)], K/V stored pre-split.
// ---------------------------------------------------------------------------
__global__ void __launch_bounds__(256)
qkv_mma_kernel(const float* __restrict__ x, const float* __restrict__ wq) {
    int b = blockIdx.z, n0 = blockIdx.y * 128;
    int jblk = blockIdx.x, j0 = jblk * 128;
    const float* xb = x + (size_t)b * ND * NN;

    __shared__ float Ah[128][20], Al[128][20];   // rx tile [n][d16]
    __shared__ float Bh[128][20], Bl[128][20];   // W  tile [j][d16]

    int tid = threadIdx.x, warp = tid >> 5, lane = tid & 31;
    int g = lane >> 2, jj = lane & 3;
    int wm = (warp & 3) * 32;    // n offset
    int wn = (warp >> 2) * 64;   // j offset

    float acc[2][8][4] = {};

    // loaders: thread -> row (tid&127), k-half (tid>>7)*8
    int arow = tid & 127, adg = (tid >> 7) * 8;
    int jglob = j0 + arow;
    const float* wrow = (jglob < 512) ? (wq + (size_t)jglob * ND)
                                      : (g_wkv + (size_t)(jglob - 512) * ND);

    float px[8];
    float4 pw[2];
    #pragma unroll
    for (int i = 0; i < 8; i++) px[i] = xb[(size_t)(adg + i) * NN + n0 + arow];
    pw[0] = *(const float4*)&wrow[adg];
    pw[1] = *(const float4*)&wrow[adg + 4];

    for (int c = 0; c < 32; c++) {
        // store prefetched chunk c (split at store)
        #pragma unroll
        for (int q = 0; q < 2; q++) {
            float2 s0 = tf32_split(px[q * 4 + 0]);
            float2 s1 = tf32_split(px[q * 4 + 1]);
            float2 s2 = tf32_split(px[q * 4 + 2]);
            float2 s3 = tf32_split(px[q * 4 + 3]);
            *(float4*)&Ah[arow][adg + q * 4] = make_float4(s0.x, s1.x, s2.x, s3.x);
            *(float4*)&Al[arow][adg + q * 4] = make_float4(s0.y, s1.y, s2.y, s3.y);
            float2 t0 = tf32_split(q ? pw[1].x : pw[0].x);
            float2 t1 = tf32_split(q ? pw[1].y : pw[0].y);
            float2 t2 = tf32_split(q ? pw[1].z : pw[0].z);
            float2 t3 = tf32_split(q ? pw[1].w : pw[0].w);
            *(float4*)&Bh[arow][adg + q * 4] = make_float4(t0.x, t1.x, t2.x, t3.x);
            *(float4*)&Bl[arow][adg + q * 4] = make_float4(t0.y, t1.y, t2.y, t3.y);
        }
        __syncthreads();

        // prefetch chunk c+1
        if (c + 1 < 32) {
            int d0 = (c + 1) * 16;
            #pragma unroll
            for (int i = 0; i < 8; i++)
                px[i] = xb[(size_t)(d0 + adg + i) * NN + n0 + arow];
            pw[0] = *(const float4*)&wrow[d0 + adg];
            pw[1] = *(const float4*)&wrow[d0 + adg + 4];
        }

        // compute chunk c
        #pragma unroll
        for (int kc = 0; kc < 2; kc++) {
            int k0 = kc * 8;
            unsigned ah[2][4], al[2][4];
            #pragma unroll
            for (int mt = 0; mt < 2; mt++) {
                int r = wm + mt * 16;
                ah[mt][0] = __float_as_uint(Ah[r + g][k0 + jj]);
                ah[mt][1] = __float_as_uint(Ah[r + g + 8][k0 + jj]);
                ah[mt][2] = __float_as_uint(Ah[r + g][k0 + jj + 4]);
                ah[mt][3] = __float_as_uint(Ah[r + g + 8][k0 + jj + 4]);
                al[mt][0] = __float_as_uint(Al[r + g][k0 + jj]);
                al[mt][1] = __float_as_uint(Al[r + g + 8][k0 + jj]);
                al[mt][2] = __float_as_uint(Al[r + g][k0 + jj + 4]);
                al[mt][3] = __float_as_uint(Al[r + g + 8][k0 + jj + 4]);
            }
            #pragma unroll
            for (int nt = 0; nt < 8; nt++) {
                int r = wn + nt * 8 + g;
                unsigned bh0 = __float_as_uint(Bh[r][k0 + jj]);
                unsigned bh1 = __float_as_uint(Bh[r][k0 + jj + 4]);
                unsigned bl0 = __float_as_uint(Bl[r][k0 + jj]);
                unsigned bl1 = __float_as_uint(Bl[r][k0 + jj + 4]);
                #pragma unroll
                for (int mt = 0; mt < 2; mt++) {
                    mma_tf32(acc[mt][nt], ah[mt], bh0, bh1);
                    mma_tf32(acc[mt][nt], ah[mt], bl0, bl1);
                    mma_tf32(acc[mt][nt], al[mt], bh0, bh1);
                }
            }
        }
        __syncthreads();
    }

    // epilogue: Q plain; K/V stored pre-split (hi/lo) for the attention stage
    #pragma unroll
    for (int mt = 0; mt < 2; mt++) {
        int n = n0 + wm + mt * 16 + g;
        size_t bn0 = (size_t)(b * NN + n);
        size_t bn1 = bn0 + 8;
        #pragma unroll
        for (int nt = 0; nt < 8; nt++) {
            int jl = wn + nt * 8 + 2 * jj;
            float2 v0 = make_float2(acc[mt][nt][0], acc[mt][nt][1]);
            float2 v1 = make_float2(acc[mt][nt][2], acc[mt][nt][3]);
            if (jblk < 4) {
                *(float2*)&g_q[bn0 * ND + j0 + jl] = v0;
                *(float2*)&g_q[bn1 * ND + j0 + jl] = v1;
            } else {
                float2 a0 = tf32_split(v0.x), a1 = tf32_split(v0.y);
                float2 b0 = tf32_split(v1.x), b1 = tf32_split(v1.y);
                if (jl < 64) {
                    *(float2*)&g_kh[bn0 * KD + jl] = make_float2(a0.x, a1.x);
                    *(float2*)&g_kl[bn0 * KD + jl] = make_float2(a0.y, a1.y);
                    *(float2*)&g_kh[bn1 * KD + jl] = make_float2(b0.x, b1.x);
                    *(float2*)&g_kl[bn1 * KD + jl] = make_float2(b0.y, b1.y);
                } else {
                    int v = jl - 64;
                    *(float2*)&g_vh[bn0 * KD + v] = make_float2(a0.x, a1.x);
                    *(float2*)&g_vl[bn0 * KD + v] = make_float2(a0.y, a1.y);
                    *(float2*)&g_vh[bn1 * KD + v] = make_float2(b0.x, b1.x);
                    *(float2*)&g_vl[bn1 * KD + v] = make_float2(b0.y, b1.y);
                }
            }
        }
    }
}

// ---------------------------------------------------------------------------
// Kernel 3: flash attention, split-tf32 mma.sync.
// K/V arrive pre-split from kernel 2 -> staging is pure float4 copies.
// S = QK^T: 3-MMA split; PV: 2-MMA (ph*vh + ph*vl).
// Grid (16 q-tiles, 8 heads, 8 batch), 128 threads.
// ---------------------------------------------------------------------------
__global__ void __launch_bounds__(128) attn_mma_kernel() {
    int b = blockIdx.z, h = blockIdx.y;
    int n0 = blockIdx.x * 64;
    int tid = threadIdx.x;
    int warp = tid >> 5, lane = tid & 31;
    int g = lane >> 2, jj = lane & 3;
    int mw = warp * 16;

    __shared__ float Kh[32 * 68], Kl[32 * 68];
    __shared__ float Vh[32 * 72], Vl[32 * 72];

    unsigned qh[8][4], ql[8][4];
    {
        const float* qbase = g_q + ((size_t)(b * NN) + n0 + mw) * ND + h * KD;
        #pragma unroll
        for (int kc = 0; kc < 8; kc++) {
            float xx[4];
            xx[0] = qbase[(size_t)g * ND + kc * 8 + jj];
            xx[1] = qbase[(size_t)(g + 8) * ND + kc * 8 + jj];
            xx[2] = qbase[(size_t)g * ND + kc * 8 + jj + 4];
            xx[3] = qbase[(size_t)(g + 8) * ND + kc * 8 + jj + 4];
            #pragma unroll
            for (int i = 0; i < 4; i++) {
                float2 sp = tf32_split(xx[i] * 0.125f);
                qh[kc][i] = __float_as_uint(sp.x);
                ql[kc][i] = __float_as_uint(sp.y);
            }
        }
    }

    float o[8][4];
    #pragma unroll
    for (int t = 0; t < 8; t++) { o[t][0] = o[t][1] = o[t][2] = o[t][3] = 0.f; }
    float m0 = -1e30f, m1 = -1e30f, l0 = 0.f, l1 = 0.f;

    for (int kb = 0; kb < 32; kb++) {
        __syncthreads();
        {   // pure-copy staging of pre-split K/V
            size_t base = ((size_t)b * NN + kb * 32) * KD;
            const float4* khp = (const float4*)(g_kh + base);
            const float4* klp = (const float4*)(g_kl + base);
            const float4* vhp = (const float4*)(g_vh + base);
            const float4* vlp = (const float4*)(g_vl + base);
            #pragma unroll
            for (int r = 0; r < 4; r++) {
                int lid = tid + 128 * r;
                int key = lid >> 4, d4 = lid & 15;
                *(float4*)&Kh[key * 68 + d4 * 4] = khp[key * 16 + d4];
                *(float4*)&Kl[key * 68 + d4 * 4] = klp[key * 16 + d4];
                *(float4*)&Vh[key * 72 + d4 * 4] = vhp[key * 16 + d4];
                *(float4*)&Vl[key * 72 + d4 * 4] = vlp[key * 16 + d4];
            }
        }
        __syncthreads();

        float s[4][4];
        #pragma unroll
        for (int nt = 0; nt < 4; nt++) s[nt][0] = s[nt][1] = s[nt][2] = s[nt][3] = 0.f;

        #pragma unroll
        for (int kc = 0; kc < 8; kc++) {
            unsigned bh0[4], bh1[4], bl0[4], bl1[4];
            #pragma unroll
            for (int nt = 0; nt < 4; nt++) {
                int idx = (nt * 8 + g) * 68 + kc * 8 + jj;
                bh0[nt] = __float_as_uint(Kh[idx]);
                bh1[nt] = __float_as_uint(Kh[idx + 4]);
                bl0[nt] = __float_as_uint(Kl[idx]);
                bl1[nt] = __float_as_uint(Kl[idx + 4]);
            }
            #pragma unroll
            for (int nt = 0; nt < 4; nt++) mma_tf32(s[nt], qh[kc], bh0[nt], bh1[nt]);
            #pragma unroll
            for (int nt = 0; nt < 4; nt++) mma_tf32(s[nt], qh[kc], bl0[nt], bl1[nt]);
            #pragma unroll
            for (int nt = 0; nt < 4; nt++) mma_tf32(s[nt], ql[kc], bh0[nt], bh1[nt]);
        }

        float rm0 = -1e30f, rm1 = -1e30f;
        #pragma unroll
        for (int nt = 0; nt < 4; nt++) {
            rm0 = fmaxf(rm0, fmaxf(s[nt][0], s[nt][1]));
            rm1 = fmaxf(rm1, fmaxf(s[nt][2], s[nt][3]));
        }
        rm0 = fmaxf(rm0, __shfl_xor_sync(0xffffffffu, rm0, 1));
        rm0 = fmaxf(rm0, __shfl_xor_sync(0xffffffffu, rm0, 2));
        rm1 = fmaxf(rm1, __shfl_xor_sync(0xffffffffu, rm1, 1));
        rm1 = fmaxf(rm1, __shfl_xor_sync(0xffffffffu, rm1, 2));
        float mn0 = fmaxf(m0, rm0), mn1 = fmaxf(m1, rm1);
        float c0 = __expf(m0 - mn0), c1 = __expf(m1 - mn1);
        m0 = mn0; m1 = mn1;
        float sum0 = 0.f, sum1 = 0.f;
        #pragma unroll
        for (int nt = 0; nt < 4; nt++) {
            s[nt][0] = __expf(s[nt][0] - m0); sum0 += s[nt][0];
            s[nt][1] = __expf(s[nt][1] - m0); sum0 += s[nt][1];
            s[nt][2] = __expf(s[nt][2] - m1); sum1 += s[nt][2];
            s[nt][3] = __expf(s[nt][3] - m1); sum1 += s[nt][3];
        }
        l0 = l0 * c0 + sum0;
        l1 = l1 * c1 + sum1;
        #pragma unroll
        for (int t = 0; t < 8; t++) {
            o[t][0] *= c0; o[t][1] *= c0; o[t][2] *= c1; o[t][3] *= c1;
        }

        // O += P V, P in tf32-hi (2-MMA: ph*vh + ph*vl)
        #pragma unroll
        for (int kc = 0; kc < 4; kc++) {
            int s0l = (lane & 28) | (jj >> 1);
            int s1l = s0l + 2;
            float t00 = __shfl_sync(0xffffffffu, s[kc][0], s0l);
            float t01 = __shfl_sync(0xffffffffu, s[kc][1], s0l);
            float t20 = __shfl_sync(0xffffffffu, s[kc][2], s0l);
            float t21 = __shfl_sync(0xffffffffu, s[kc][3], s0l);
            float u00 = __shfl_sync(0xffffffffu, s[kc][0], s1l);
            float u01 = __shfl_sync(0xffffffffu, s[kc][1], s1l);
            float u20 = __shfl_sync(0xffffffffu, s[kc][2], s1l);
            float u21 = __shfl_sync(0xffffffffu, s[kc][3], s1l);
            bool od = (jj & 1) != 0;
            unsigned ah[4];
            ah[0] = tf32_hi(od ? t01 : t00);
            ah[1] = tf32_hi(od ? t21 : t20);
            ah[2] = tf32_hi(od ? u01 : u00);
            ah[3] = tf32_hi(od ? u21 : u20);

            #pragma unroll
            for (int vt = 0; vt < 8; vt++) {
                int idx  = (kc * 8 + jj) * 72 + vt * 8 + g;
                int idx4 = idx + 4 * 72;
                unsigned b0h = __float_as_uint(Vh[idx]);
                unsigned b1h = __float_as_uint(Vh[idx4]);
                unsigned b0l = __float_as_uint(Vl[idx]);
                unsigned b1l = __float_as_uint(Vl[idx4]);
                mma_tf32(o[vt], ah, b0h, b1h);
                mma_tf32(o[vt], ah, b0l, b1l);
            }
        }
    }

    l0 += __shfl_xor_sync(0xffffffffu, l0, 1);
    l0 += __shfl_xor_sync(0xffffffffu, l0, 2);
    l1 += __shfl_xor_sync(0xffffffffu, l1, 1);
    l1 += __shfl_xor_sync(0xffffffffu, l1, 2);
    float inv0 = 1.0f / l0, inv1 = 1.0f / l1;

    float* ob = g_o + ((size_t)(b * NN) + n0 + mw) * ND + h * KD;
    #pragma unroll
    for (int vt = 0; vt < 8; vt++) {
        ob[(size_t)g * ND + vt * 8 + 2 * jj]           = o[vt][0] * inv0;
        ob[(size_t)g * ND + vt * 8 + 2 * jj + 1]       = o[vt][1] * inv0;
        ob[(size_t)(g + 8) * ND + vt * 8 + 2 * jj]     = o[vt][2] * inv1;
        ob[(size_t)(g + 8) * ND + vt * 8 + 2 * jj + 1] = o[vt][3] * inv1;
    }
}

// ---------------------------------------------------------------------------
// Kernel 4: output projection, split-tf32 mma.sync, m32n64 warp tiles.
// out[b][dout][n] = sum_j wout[dout][j] * g_o[b][n][j]
// CTA: 128(dout) x 128(n), 8 warps (4m x 2n), K-chunk 16, reg prefetch.
// Grid (8 ntile, 4 dtile, 8 b), 256 threads.
// ---------------------------------------------------------------------------
__global__ void __launch_bounds__(256)
out_mma_kernel(const float* __restrict__ wout, float* __restrict__ out) {
    int b = blockIdx.z;
    int do0 = blockIdx.y * 128;
    int n0  = blockIdx.x * 128;

    __shared__ float Wh[128][20], Wl[128][20];   // [dout][j16]
    __shared__ float Oh[128][20], Ol[128][20];   // [n][j16]

    int tid = threadIdx.x, warp = tid >> 5, lane = tid & 31;
    int g = lane >> 2, jj = lane & 3;
    int wm = (warp & 3) * 32;    // dout offset
    int wn = (warp >> 2) * 64;   // n offset

    float acc[2][8][4] = {};

    int arow = tid & 127, adg = (tid >> 7) * 8;
    const float* wrow = wout + (size_t)(do0 + arow) * ND;
    const float* orow = g_o + ((size_t)(b * NN) + n0 + arow) * ND;

    float4 pw[2], po[2];
    pw[0] = *(const float4*)&wrow[adg];
    pw[1] = *(const float4*)&wrow[adg + 4];
    po[0] = *(const float4*)&orow[adg];
    po[1] = *(const float4*)&orow[adg + 4];

    for (int c = 0; c < 32; c++) {
        #pragma unroll
        for (int q = 0; q < 2; q++) {
            float2 s0 = tf32_split(q ? pw[1].x : pw[0].x);
            float2 s1 = tf32_split(q ? pw[1].y : pw[0].y);
            float2 s2 = tf32_split(q ? pw[1].z : pw[0].z);
            float2 s3 = tf32_split(q ? pw[1].w : pw[0].w);
            *(float4*)&Wh[arow][adg + q * 4] = make_float4(s0.x, s1.x, s2.x, s3.x);
            *(float4*)&Wl[arow][adg + q * 4] = make_float4(s0.y, s1.y, s2.y, s3.y);
            float2 t0 = tf32_split(q ? po[1].x : po[0].x);
            float2 t1 = tf32_split(q ? po[1].y : po[0].y);
            float2 t2 = tf32_split(q ? po[1].z : po[0].z);
            float2 t3 = tf32_split(q ? po[1].w : po[0].w);
            *(float4*)&Oh[arow][adg + q * 4] = make_float4(t0.x, t1.x, t2.x, t3.x);
            *(float4*)&Ol[arow][adg + q * 4] = make_float4(t0.y, t1.y, t2.y, t3.y);
        }
        __syncthreads();

        if (c + 1 < 32) {
            int j0 = (c + 1) * 16;
            pw[0] = *(const float4*)&wrow[j0 + adg];
            pw[1] = *(const float4*)&wrow[j0 + adg + 4];
            po[0] = *(const float4*)&orow[j0 + adg];
            po[1] = *(const float4*)&orow[j0 + adg + 4];
        }

        #pragma unroll
        for (int kc = 0; kc < 2; kc++) {
            int k0 = kc * 8;
            unsigned ah[2][4], al[2][4];
            #pragma unroll
            for (int mt = 0; mt < 2; mt++) {
                int r = wm + mt * 16;
                ah[mt][0] = __float_as_uint(Wh[r + g][k0 + jj]);
                ah[mt][1] = __float_as_uint(Wh[r + g + 8][k0 + jj]);
                ah[mt][2] = __float_as_uint(Wh[r + g][k0 + jj + 4]);
                ah[mt][3] = __float_as_uint(Wh[r + g + 8][k0 + jj + 4]);
                al[mt][0] = __float_as_uint(Wl[r + g][k0 + jj]);
                al[mt][1] = __float_as_uint(Wl[r + g + 8][k0 + jj]);
                al[mt][2] = __float_as_uint(Wl[r + g][k0 + jj + 4]);
                al[mt][3] = __float_as_uint(Wl[r + g + 8][k0 + jj + 4]);
            }
            #pragma unroll
            for (int nt = 0; nt < 8; nt++) {
                int r = wn + nt * 8 + g;
                unsigned bh0 = __float_as_uint(Oh[r][k0 + jj]);
                unsigned bh1 = __float_as_uint(Oh[r][k0 + jj + 4]);
                unsigned bl0 = __float_as_uint(Ol[r][k0 + jj]);
                unsigned bl1 = __float_as_uint(Ol[r][k0 + jj + 4]);
                #pragma unroll
                for (int mt = 0; mt < 2; mt++) {
                    mma_tf32(acc[mt][nt], ah[mt], bh0, bh1);
                    mma_tf32(acc[mt][nt], ah[mt], bl0, bl1);
                    mma_tf32(acc[mt][nt], al[mt], bh0, bh1);
                }
            }
        }
        __syncthreads();
    }

    #pragma unroll
    for (int mt = 0; mt < 2; mt++) {
        int d0r = do0 + wm + mt * 16 + g;
        #pragma unroll
        for (int nt = 0; nt < 8; nt++) {
            int col = n0 + wn + nt * 8 + 2 * jj;
            *(float2*)&out[((size_t)b * ND + d0r) * NN + col] =
                make_float2(acc[mt][nt][0], acc[mt][nt][1]);
            *(float2*)&out[((size_t)b * ND + d0r + 8) * NN + col] =
                make_float2(acc[mt][nt][2], acc[mt][nt][3]);
        }
    }
}

// ---------------------------------------------------------------------------
// Launch
// ---------------------------------------------------------------------------
extern "C" void kernel_launch(void* const* d_in, const int* in_sizes, int n_in,
                              void* d_out, int out_size) {
    const float* x  = (const float*)d_in[0];  // [8, 512, 32, 32]
    const float* wq = (const float*)d_in[1];  // [8, 64, 512]
    const float* wk = (const float*)d_in[2];  // [512, 64]
    const float* wv = (const float*)d_in[3];  // [512, 64]
    const float* wo = (const float*)d_in[4];  // [512, 8, 64]
    float* out      = (float*)d_out;          // [8, 512, 32, 32]

    pack_wkv_kernel<<<256, 256>>>(wk, wv);
    qkv_mma_kernel<<<dim3(5, 8, NB), 256>>>(x, wq);
    attn_mma_kernel<<<dim3(16, NH, NB), 128>>>();
    out_mma_kernel<<<dim3(8, 4, NB), 256>>>(wo, out);
}

// round 17
// speedup vs baseline: 1.0433x; 1.0433x over previous
#include <cuda_runtime.h>
#include <cstdint>

#define NB 8
#define ND 512
#define NN 1024
#define NH 8
#define KD 64

__device__ float g_q[NB * NN * ND];
__device__ float g_kh[NB * NN * KD];
__device__ float g_kl[NB * NN * KD];
__device__ float g_vh[NB * NN * KD];
__device__ float g_vl[NB * NN * KD];
__device__ float g_o[NB * NN * ND];
__device__ float g_wkv[128 * ND];

// ---------------------------------------------------------------------------
// helpers
// ---------------------------------------------------------------------------
__device__ __forceinline__ float2 tf32_split(float x) {
    unsigned h, l;
    asm("cvt.rna.tf32.f32 %0, %1;" : "=r"(h) : "f"(x));
    float r = x - __uint_as_float(h);
    asm("cvt.rna.tf32.f32 %0, %1;" : "=r"(l) : "f"(r));
    return make_float2(__uint_as_float(h), __uint_as_float(l));
}

__device__ __forceinline__ unsigned tf32_hi(float x) {
    unsigned h;
    asm("cvt.rna.tf32.f32 %0, %1;" : "=r"(h) : "f"(x));
    return h;
}

__device__ __forceinline__ void mma_tf32(float* d, const unsigned* a,
                                         unsigned b0, unsigned b1) {
    asm("mma.sync.aligned.m16n8k8.row.col.f32.tf32.tf32.f32 "
        "{%0,%1,%2,%3}, {%4,%5,%6,%7}, {%8,%9}, {%0,%1,%2,%3};"
        : "+f"(d[0]), "+f"(d[1]), "+f"(d[2]), "+f"(d[3])
        : "r"(a[0]), "r"(a[1]), "r"(a[2]), "r"(a[3]), "r"(b0), "r"(b1));
}

// ---------------------------------------------------------------------------
// Kernel 1: pack wk/wv into row-major [j][d]
// ---------------------------------------------------------------------------
__global__ void pack_wkv_kernel(const float* __restrict__ kp,
                                const float* __restrict__ vp) {
    int idx = blockIdx.x * 256 + threadIdx.x;
    int j = idx >> 9, d = idx & 511;
    g_wkv[idx] = (j < 64) ? kp[d * 64 + j] : vp[d * 64 + (j - 64)];
}

// ---------------------------------------------------------------------------
// Kernel 2: QKV projection, split-tf32 mma.sync (3-MMA), m32n64 warp tiles.
// CTA: 128(n) x 128(j), 8 warps (4m x 2n), K-chunk 16, reg prefetch.
// __launch_bounds__(256,2) caps regs at 128 -> 2 CTAs/SM.
// Grid (5 jt, 8 nt, 8 b), 256 threads.
// ---------------------------------------------------------------------------
__global__ void __launch_bounds__(256, 2)
qkv_mma_kernel(const float* __restrict__ x, const float* __restrict__ wq) {
    int b = blockIdx.z, n0 = blockIdx.y * 128;
    int jblk = blockIdx.x, j0 = jblk * 128;
    const float* xb = x + (size_t)b * ND * NN;

    __shared__ float Ah[128][20], Al[128][20];   // rx tile [n][d16]
    __shared__ float Bh[128][20], Bl[128][20];   // W  tile [j][d16]

    int tid = threadIdx.x, warp = tid >> 5, lane = tid & 31;
    int g = lane >> 2, jj = lane & 3;
    int wm = (warp & 3) * 32;    // n offset
    int wn = (warp >> 2) * 64;   // j offset

    float acc[2][8][4] = {};

    int arow = tid & 127, adg = (tid >> 7) * 8;
    int jglob = j0 + arow;
    const float* wrow = (jglob < 512) ? (wq + (size_t)jglob * ND)
                                      : (g_wkv + (size_t)(jglob - 512) * ND);

    float px[8];
    float4 pw[2];
    #pragma unroll
    for (int i = 0; i < 8; i++) px[i] = xb[(size_t)(adg + i) * NN + n0 + arow];
    pw[0] = *(const float4*)&wrow[adg];
    pw[1] = *(const float4*)&wrow[adg + 4];

    for (int c = 0; c < 32; c++) {
        #pragma unroll
        for (int q = 0; q < 2; q++) {
            float2 s0 = tf32_split(px[q * 4 + 0]);
            float2 s1 = tf32_split(px[q * 4 + 1]);
            float2 s2 = tf32_split(px[q * 4 + 2]);
            float2 s3 = tf32_split(px[q * 4 + 3]);
            *(float4*)&Ah[arow][adg + q * 4] = make_float4(s0.x, s1.x, s2.x, s3.x);
            *(float4*)&Al[arow][adg + q * 4] = make_float4(s0.y, s1.y, s2.y, s3.y);
            float2 t0 = tf32_split(q ? pw[1].x : pw[0].x);
            float2 t1 = tf32_split(q ? pw[1].y : pw[0].y);
            float2 t2 = tf32_split(q ? pw[1].z : pw[0].z);
            float2 t3 = tf32_split(q ? pw[1].w : pw[0].w);
            *(float4*)&Bh[arow][adg + q * 4] = make_float4(t0.x, t1.x, t2.x, t3.x);
            *(float4*)&Bl[arow][adg + q * 4] = make_float4(t0.y, t1.y, t2.y, t3.y);
        }
        __syncthreads();

        if (c + 1 < 32) {
            int d0 = (c + 1) * 16;
            #pragma unroll
            for (int i = 0; i < 8; i++)
                px[i] = xb[(size_t)(d0 + adg + i) * NN + n0 + arow];
            pw[0] = *(const float4*)&wrow[d0 + adg];
            pw[1] = *(const float4*)&wrow[d0 + adg + 4];
        }

        #pragma unroll
        for (int kc = 0; kc < 2; kc++) {
            int k0 = kc * 8;
            unsigned ah[2][4], al[2][4];
            #pragma unroll
            for (int mt = 0; mt < 2; mt++) {
                int r = wm + mt * 16;
                ah[mt][0] = __float_as_uint(Ah[r + g][k0 + jj]);
                ah[mt][1] = __float_as_uint(Ah[r + g + 8][k0 + jj]);
                ah[mt][2] = __float_as_uint(Ah[r + g][k0 + jj + 4]);
                ah[mt][3] = __float_as_uint(Ah[r + g + 8][k0 + jj + 4]);
                al[mt][0] = __float_as_uint(Al[r + g][k0 + jj]);
                al[mt][1] = __float_as_uint(Al[r + g + 8][k0 + jj]);
                al[mt][2] = __float_as_uint(Al[r + g][k0 + jj + 4]);
                al[mt][3] = __float_as_uint(Al[r + g + 8][k0 + jj + 4]);
            }
            #pragma unroll
            for (int nt = 0; nt < 8; nt++) {
                int r = wn + nt * 8 + g;
                unsigned bh0 = __float_as_uint(Bh[r][k0 + jj]);
                unsigned bh1 = __float_as_uint(Bh[r][k0 + jj + 4]);
                unsigned bl0 = __float_as_uint(Bl[r][k0 + jj]);
                unsigned bl1 = __float_as_uint(Bl[r][k0 + jj + 4]);
                #pragma unroll
                for (int mt = 0; mt < 2; mt++) {
                    mma_tf32(acc[mt][nt], ah[mt], bh0, bh1);
                    mma_tf32(acc[mt][nt], ah[mt], bl0, bl1);
                    mma_tf32(acc[mt][nt], al[mt], bh0, bh1);
                }
            }
        }
        __syncthreads();
    }

    #pragma unroll
    for (int mt = 0; mt < 2; mt++) {
        int n = n0 + wm + mt * 16 + g;
        size_t bn0 = (size_t)(b * NN + n);
        size_t bn1 = bn0 + 8;
        #pragma unroll
        for (int nt = 0; nt < 8; nt++) {
            int jl = wn + nt * 8 + 2 * jj;
            float2 v0 = make_float2(acc[mt][nt][0], acc[mt][nt][1]);
            float2 v1 = make_float2(acc[mt][nt][2], acc[mt][nt][3]);
            if (jblk < 4) {
                *(float2*)&g_q[bn0 * ND + j0 + jl] = v0;
                *(float2*)&g_q[bn1 * ND + j0 + jl] = v1;
            } else {
                float2 a0 = tf32_split(v0.x), a1 = tf32_split(v0.y);
                float2 b0 = tf32_split(v1.x), b1 = tf32_split(v1.y);
                if (jl < 64) {
                    *(float2*)&g_kh[bn0 * KD + jl] = make_float2(a0.x, a1.x);
                    *(float2*)&g_kl[bn0 * KD + jl] = make_float2(a0.y, a1.y);
                    *(float2*)&g_kh[bn1 * KD + jl] = make_float2(b0.x, b1.x);
                    *(float2*)&g_kl[bn1 * KD + jl] = make_float2(b0.y, b1.y);
                } else {
                    int v = jl - 64;
                    *(float2*)&g_vh[bn0 * KD + v] = make_float2(a0.x, a1.x);
                    *(float2*)&g_vl[bn0 * KD + v] = make_float2(a0.y, a1.y);
                    *(float2*)&g_vh[bn1 * KD + v] = make_float2(b0.x, b1.x);
                    *(float2*)&g_vl[bn1 * KD + v] = make_float2(b0.y, b1.y);
                }
            }
        }
    }
}

// ---------------------------------------------------------------------------
// Kernel 3: flash attention, split-tf32 mma.sync (unchanged from R16).
// K/V pre-split -> staging is pure float4 copies.
// S: 3-MMA split; PV: 2-MMA (ph*vh + ph*vl).
// ---------------------------------------------------------------------------
__global__ void __launch_bounds__(128) attn_mma_kernel() {
    int b = blockIdx.z, h = blockIdx.y;
    int n0 = blockIdx.x * 64;
    int tid = threadIdx.x;
    int warp = tid >> 5, lane = tid & 31;
    int g = lane >> 2, jj = lane & 3;
    int mw = warp * 16;

    __shared__ float Kh[32 * 68], Kl[32 * 68];
    __shared__ float Vh[32 * 72], Vl[32 * 72];

    unsigned qh[8][4], ql[8][4];
    {
        const float* qbase = g_q + ((size_t)(b * NN) + n0 + mw) * ND + h * KD;
        #pragma unroll
        for (int kc = 0; kc < 8; kc++) {
            float xx[4];
            xx[0] = qbase[(size_t)g * ND + kc * 8 + jj];
            xx[1] = qbase[(size_t)(g + 8) * ND + kc * 8 + jj];
            xx[2] = qbase[(size_t)g * ND + kc * 8 + jj + 4];
            xx[3] = qbase[(size_t)(g + 8) * ND + kc * 8 + jj + 4];
            #pragma unroll
            for (int i = 0; i < 4; i++) {
                float2 sp = tf32_split(xx[i] * 0.125f);
                qh[kc][i] = __float_as_uint(sp.x);
                ql[kc][i] = __float_as_uint(sp.y);
            }
        }
    }

    float o[8][4];
    #pragma unroll
    for (int t = 0; t < 8; t++) { o[t][0] = o[t][1] = o[t][2] = o[t][3] = 0.f; }
    float m0 = -1e30f, m1 = -1e30f, l0 = 0.f, l1 = 0.f;

    for (int kb = 0; kb < 32; kb++) {
        __syncthreads();
        {
            size_t base = ((size_t)b * NN + kb * 32) * KD;
            const float4* khp = (const float4*)(g_kh + base);
            const float4* klp = (const float4*)(g_kl + base);
            const float4* vhp = (const float4*)(g_vh + base);
            const float4* vlp = (const float4*)(g_vl + base);
            #pragma unroll
            for (int r = 0; r < 4; r++) {
                int lid = tid + 128 * r;
                int key = lid >> 4, d4 = lid & 15;
                *(float4*)&Kh[key * 68 + d4 * 4] = khp[key * 16 + d4];
                *(float4*)&Kl[key * 68 + d4 * 4] = klp[key * 16 + d4];
                *(float4*)&Vh[key * 72 + d4 * 4] = vhp[key * 16 + d4];
                *(float4*)&Vl[key * 72 + d4 * 4] = vlp[key * 16 + d4];
            }
        }
        __syncthreads();

        float s[4][4];
        #pragma unroll
        for (int nt = 0; nt < 4; nt++) s[nt][0] = s[nt][1] = s[nt][2] = s[nt][3] = 0.f;

        #pragma unroll
        for (int kc = 0; kc < 8; kc++) {
            unsigned bh0[4], bh1[4], bl0[4], bl1[4];
            #pragma unroll
            for (int nt = 0; nt < 4; nt++) {
                int idx = (nt * 8 + g) * 68 + kc * 8 + jj;
                bh0[nt] = __float_as_uint(Kh[idx]);
                bh1[nt] = __float_as_uint(Kh[idx + 4]);
                bl0[nt] = __float_as_uint(Kl[idx]);
                bl1[nt] = __float_as_uint(Kl[idx + 4]);
            }
            #pragma unroll
            for (int nt = 0; nt < 4; nt++) mma_tf32(s[nt], qh[kc], bh0[nt], bh1[nt]);
            #pragma unroll
            for (int nt = 0; nt < 4; nt++) mma_tf32(s[nt], qh[kc], bl0[nt], bl1[nt]);
            #pragma unroll
            for (int nt = 0; nt < 4; nt++) mma_tf32(s[nt], ql[kc], bh0[nt], bh1[nt]);
        }

        float rm0 = -1e30f, rm1 = -1e30f;
        #pragma unroll
        for (int nt = 0; nt < 4; nt++) {
            rm0 = fmaxf(rm0, fmaxf(s[nt][0], s[nt][1]));
            rm1 = fmaxf(rm1, fmaxf(s[nt][2], s[nt][3]));
        }
        rm0 = fmaxf(rm0, __shfl_xor_sync(0xffffffffu, rm0, 1));
        rm0 = fmaxf(rm0, __shfl_xor_sync(0xffffffffu, rm0, 2));
        rm1 = fmaxf(rm1, __shfl_xor_sync(0xffffffffu, rm1, 1));
        rm1 = fmaxf(rm1, __shfl_xor_sync(0xffffffffu, rm1, 2));
        float mn0 = fmaxf(m0, rm0), mn1 = fmaxf(m1, rm1);
        float c0 = __expf(m0 - mn0), c1 = __expf(m1 - mn1);
        m0 = mn0; m1 = mn1;
        float sum0 = 0.f, sum1 = 0.f;
        #pragma unroll
        for (int nt = 0; nt < 4; nt++) {
            s[nt][0] = __expf(s[nt][0] - m0); sum0 += s[nt][0];
            s[nt][1] = __expf(s[nt][1] - m0); sum0 += s[nt][1];
            s[nt][2] = __expf(s[nt][2] - m1); sum1 += s[nt][2];
            s[nt][3] = __expf(s[nt][3] - m1); sum1 += s[nt][3];
        }
        l0 = l0 * c0 + sum0;
        l1 = l1 * c1 + sum1;
        #pragma unroll
        for (int t = 0; t < 8; t++) {
            o[t][0] *= c0; o[t][1] *= c0; o[t][2] *= c1; o[t][3] *= c1;
        }

        #pragma unroll
        for (int kc = 0; kc < 4; kc++) {
            int s0l = (lane & 28) | (jj >> 1);
            int s1l = s0l + 2;
            float t00 = __shfl_sync(0xffffffffu, s[kc][0], s0l);
            float t01 = __shfl_sync(0xffffffffu, s[kc][1], s0l);
            float t20 = __shfl_sync(0xffffffffu, s[kc][2], s0l);
            float t21 = __shfl_sync(0xffffffffu, s[kc][3], s0l);
            float u00 = __shfl_sync(0xffffffffu, s[kc][0], s1l);
            float u01 = __shfl_sync(0xffffffffu, s[kc][1], s1l);
            float u20 = __shfl_sync(0xffffffffu, s[kc][2], s1l);
            float u21 = __shfl_sync(0xffffffffu, s[kc][3], s1l);
            bool od = (jj & 1) != 0;
            unsigned ah[4];
            ah[0] = tf32_hi(od ? t01 : t00);
            ah[1] = tf32_hi(od ? t21 : t20);
            ah[2] = tf32_hi(od ? u01 : u00);
            ah[3] = tf32_hi(od ? u21 : u20);

            #pragma unroll
            for (int vt = 0; vt < 8; vt++) {
                int idx  = (kc * 8 + jj) * 72 + vt * 8 + g;
                int idx4 = idx + 4 * 72;
                unsigned b0h = __float_as_uint(Vh[idx]);
                unsigned b1h = __float_as_uint(Vh[idx4]);
                unsigned b0l = __float_as_uint(Vl[idx]);
                unsigned b1l = __float_as_uint(Vl[idx4]);
                mma_tf32(o[vt], ah, b0h, b1h);
                mma_tf32(o[vt], ah, b0l, b1l);
            }
        }
    }

    l0 += __shfl_xor_sync(0xffffffffu, l0, 1);
    l0 += __shfl_xor_sync(0xffffffffu, l0, 2);
    l1 += __shfl_xor_sync(0xffffffffu, l1, 1);
    l1 += __shfl_xor_sync(0xffffffffu, l1, 2);
    float inv0 = 1.0f / l0, inv1 = 1.0f / l1;

    float* ob = g_o + ((size_t)(b * NN) + n0 + mw) * ND + h * KD;
    #pragma unroll
    for (int vt = 0; vt < 8; vt++) {
        ob[(size_t)g * ND + vt * 8 + 2 * jj]           = o[vt][0] * inv0;
        ob[(size_t)g * ND + vt * 8 + 2 * jj + 1]       = o[vt][1] * inv0;
        ob[(size_t)(g + 8) * ND + vt * 8 + 2 * jj]     = o[vt][2] * inv1;
        ob[(size_t)(g + 8) * ND + vt * 8 + 2 * jj + 1] = o[vt][3] * inv1;
    }
}

// ---------------------------------------------------------------------------
// Kernel 4: output projection, 2-MMA split (W_hi only x full O), m32n64.
// out[b][dout][n] = sum_j wout[dout][j] * g_o[b][n][j]
// CTA: 128(dout) x 128(n), 8 warps (4m x 2n), K-chunk 16, reg prefetch.
// __launch_bounds__(256,2) -> 2 CTAs/SM. Grid (8 nt, 4 dt, 8 b).
// ---------------------------------------------------------------------------
__global__ void __launch_bounds__(256, 2)
out_mma_kernel(const float* __restrict__ wout, float* __restrict__ out) {
    int b = blockIdx.z;
    int do0 = blockIdx.y * 128;
    int n0  = blockIdx.x * 128;

    __shared__ float Wh[128][20];                // [dout][j16] (hi only)
    __shared__ float Oh[128][20], Ol[128][20];   // [n][j16]

    int tid = threadIdx.x, warp = tid >> 5, lane = tid & 31;
    int g = lane >> 2, jj = lane & 3;
    int wm = (warp & 3) * 32;    // dout offset
    int wn = (warp >> 2) * 64;   // n offset

    float acc[2][8][4] = {};

    int arow = tid & 127, adg = (tid >> 7) * 8;
    const float* wrow = wout + (size_t)(do0 + arow) * ND;
    const float* orow = g_o + ((size_t)(b * NN) + n0 + arow) * ND;

    float4 pw[2], po[2];
    pw[0] = *(const float4*)&wrow[adg];
    pw[1] = *(const float4*)&wrow[adg + 4];
    po[0] = *(const float4*)&orow[adg];
    po[1] = *(const float4*)&orow[adg + 4];

    for (int c = 0; c < 32; c++) {
        #pragma unroll
        for (int q = 0; q < 2; q++) {
            float4 w4 = q ? pw[1] : pw[0];
            *(float4*)&Wh[arow][adg + q * 4] =
                make_float4(__uint_as_float(tf32_hi(w4.x)),
                            __uint_as_float(tf32_hi(w4.y)),
                            __uint_as_float(tf32_hi(w4.z)),
                            __uint_as_float(tf32_hi(w4.w)));
            float2 t0 = tf32_split(q ? po[1].x : po[0].x);
            float2 t1 = tf32_split(q ? po[1].y : po[0].y);
            float2 t2 = tf32_split(q ? po[1].z : po[0].z);
            float2 t3 = tf32_split(q ? po[1].w : po[0].w);
            *(float4*)&Oh[arow][adg + q * 4] = make_float4(t0.x, t1.x, t2.x, t3.x);
            *(float4*)&Ol[arow][adg + q * 4] = make_float4(t0.y, t1.y, t2.y, t3.y);
        }
        __syncthreads();

        if (c + 1 < 32) {
            int j0 = (c + 1) * 16;
            pw[0] = *(const float4*)&wrow[j0 + adg];
            pw[1] = *(const float4*)&wrow[j0 + adg + 4];
            po[0] = *(const float4*)&orow[j0 + adg];
            po[1] = *(const float4*)&orow[j0 + adg + 4];
        }

        #pragma unroll
        for (int kc = 0; kc < 2; kc++) {
            int k0 = kc * 8;
            unsigned ah[2][4];
            #pragma unroll
            for (int mt = 0; mt < 2; mt++) {
                int r = wm + mt * 16;
                ah[mt][0] = __float_as_uint(Wh[r + g][k0 + jj]);
                ah[mt][1] = __float_as_uint(Wh[r + g + 8][k0 + jj]);
                ah[mt][2] = __float_as_uint(Wh[r + g][k0 + jj + 4]);
                ah[mt][3] = __float_as_uint(Wh[r + g + 8][k0 + jj + 4]);
            }
            #pragma unroll
            for (int nt = 0; nt < 8; nt++) {
                int r = wn + nt * 8 + g;
                unsigned bh0 = __float_as_uint(Oh[r][k0 + jj]);
                unsigned bh1 = __float_as_uint(Oh[r][k0 + jj + 4]);
                unsigned bl0 = __float_as_uint(Ol[r][k0 + jj]);
                unsigned bl1 = __float_as_uint(Ol[r][k0 + jj + 4]);
                #pragma unroll
                for (int mt = 0; mt < 2; mt++) {
                    mma_tf32(acc[mt][nt], ah[mt], bh0, bh1);
                    mma_tf32(acc[mt][nt], ah[mt], bl0, bl1);
                }
            }
        }
        __syncthreads();
    }

    #pragma unroll
    for (int mt = 0; mt < 2; mt++) {
        int d0r = do0 + wm + mt * 16 + g;
        #pragma unroll
        for (int nt = 0; nt < 8; nt++) {
            int col = n0 + wn + nt * 8 + 2 * jj;
            *(float2*)&out[((size_t)b * ND + d0r) * NN + col] =
                make_float2(acc[mt][nt][0], acc[mt][nt][1]);
            *(float2*)&out[((size_t)b * ND + d0r + 8) * NN + col] =
                make_float2(acc[mt][nt][2], acc[mt][nt][3]);
        }
    }
}

// ---------------------------------------------------------------------------
// Launch
// ---------------------------------------------------------------------------
extern "C" void kernel_launch(void* const* d_in, const int* in_sizes, int n_in,
                              void* d_out, int out_size) {
    const float* x  = (const float*)d_in[0];  // [8, 512, 32, 32]
    const float* wq = (const float*)d_in[1];  // [8, 64, 512]
    const float* wk = (const float*)d_in[2];  // [512, 64]
    const float* wv = (const float*)d_in[3];  // [512, 64]
    const float* wo = (const float*)d_in[4];  // [512, 8, 64]
    float* out      = (float*)d_out;          // [8, 512, 32, 32]

    pack_wkv_kernel<<<256, 256>>>(wk, wv);
    qkv_mma_kernel<<<dim3(5, 8, NB), 256>>>(x, wq);
    attn_mma_kernel<<<dim3(16, NH, NB), 128>>>();
    out_mma_kernel<<<dim3(8, 4, NB), 256>>>(wo, out);
}